// round 4
// baseline (speedup 1.0000x reference)
#include <cuda_runtime.h>
#include <cuda_bf16.h>
#include <stdint.h>
#include <float.h>
#include <math.h>

// ---------------- problem constants ----------------
#define BB   256
#define NN   129
#define CC   768
#define C4   192
#define CG   256
#define NSW  38
#define TOK  (BB*NN)   // 33024 = 258 * 128

// ---------------- device scratch (no cudaMalloc allowed) ----------------
__device__ __align__(16) __nv_bfloat16 g_W1s[3][C4*CC];   // W1^T split [192][768]
__device__ __align__(16) __nv_bfloat16 g_M2s[3][CG*C4];   // (W2@V1)^T split [256][192]
__device__ __align__(16) __nv_bfloat16 g_Hs[3][(size_t)TOK*C4]; // H split
__device__ float g_M[C4*CG];
__device__ float g_d[CG];
__device__ float g_clsn[BB*CC];
__device__ float g_part[(size_t)TOK*4];
__device__ float g_imp[TOK];
__device__ int   g_tp[BB*NSW];
__device__ int   g_swapidx[BB*2];

// ---------------- helpers ----------------
__device__ __forceinline__ uint32_t smem_u32(const void* p) {
    uint32_t a;
    asm("{ .reg .u64 t; cvta.to.shared.u64 t, %1; cvt.u32.u64 %0, t; }" : "=r"(a) : "l"(p));
    return a;
}
__device__ __forceinline__ void ldsm4(uint32_t* r, uint32_t addr) {
    asm volatile("ldmatrix.sync.aligned.m8n8.x4.shared.b16 {%0,%1,%2,%3}, [%4];"
                 : "=r"(r[0]), "=r"(r[1]), "=r"(r[2]), "=r"(r[3]) : "r"(addr));
}
__device__ __forceinline__ void ldsm2(uint32_t* r, uint32_t addr) {
    asm volatile("ldmatrix.sync.aligned.m8n8.x2.shared.b16 {%0,%1}, [%2];"
                 : "=r"(r[0]), "=r"(r[1]) : "r"(addr));
}
__device__ __forceinline__ void mma_bf16(float* c, const uint32_t* a, const uint32_t* b) {
    asm volatile("mma.sync.aligned.m16n8k16.row.col.f32.bf16.bf16.f32 "
                 "{%0,%1,%2,%3}, {%4,%5,%6,%7}, {%8,%9}, {%0,%1,%2,%3};"
                 : "+f"(c[0]), "+f"(c[1]), "+f"(c[2]), "+f"(c[3])
                 : "r"(a[0]), "r"(a[1]), "r"(a[2]), "r"(a[3]), "r"(b[0]), "r"(b[1]));
}
__device__ __forceinline__ void split3(float v, __nv_bfloat16& h, __nv_bfloat16& m,
                                       __nv_bfloat16& l) {
    h = __float2bfloat16(v);
    float r = v - __bfloat162float(h);
    m = __float2bfloat16(r);
    float r2 = r - __bfloat162float(m);
    l = __float2bfloat16(r2);
}
__device__ __forceinline__ uint32_t packbf(__nv_bfloat16 a, __nv_bfloat16 b) {
    return (uint32_t)__bfloat16_as_ushort(a) | ((uint32_t)__bfloat16_as_ushort(b) << 16);
}

// ============ split W1 (transposed) -> g_W1s ===================================
__global__ void k_splitW1(const float* __restrict__ W1) {
    int n = blockIdx.x;  // 0..191
    for (int k = threadIdx.x; k < CC; k += 256) {
        float v = W1[k * C4 + n];
        __nv_bfloat16 h, m, l; split3(v, h, m, l);
        g_W1s[0][n * CC + k] = h; g_W1s[1][n * CC + k] = m; g_W1s[2][n * CC + k] = l;
    }
}

// ============ split folded M (transposed) -> g_M2s =============================
__global__ void k_splitM() {
    int n = blockIdx.x;  // 0..255
    for (int k = threadIdx.x; k < C4; k += 192) {
        float v = g_M[k * CG + n];
        __nv_bfloat16 h, m, l; split3(v, h, m, l);
        g_M2s[0][n * C4 + k] = h; g_M2s[1][n * C4 + k] = m; g_M2s[2][n * C4 + k] = l;
    }
}

// ============ cls normalization ================================================
__global__ void k_clsnorm(const float* __restrict__ feat) {
    int b = blockIdx.x;
    const float* x = feat + (size_t)b * NN * CC;
    __shared__ float red[256];
    float s = 0.f;
    for (int c = threadIdx.x; c < CC; c += 256) { float v = x[c]; s += v * v; }
    red[threadIdx.x] = s; __syncthreads();
    for (int st = 128; st > 0; st >>= 1) {
        if (threadIdx.x < st) red[threadIdx.x] += red[threadIdx.x + st];
        __syncthreads();
    }
    float inv = 1.0f / fmaxf(sqrtf(red[0]), 1e-12f);
    for (int c = threadIdx.x; c < CC; c += 256) g_clsn[b * CC + c] = x[c] * inv;
}

// ============ fold M = W2@V1, d = b2@V1 + c1 ===================================
__global__ void k_fold(const float* __restrict__ W2, const float* __restrict__ V1,
                       const float* __restrict__ b2, const float* __restrict__ c1) {
    int j = threadIdx.x;
    if (blockIdx.x == 48) {
        float acc = c1[j];
        for (int k = 0; k < CC; k++) acc += b2[k] * V1[k * CG + j];
        g_d[j] = acc;
        return;
    }
    int i0 = blockIdx.x * 4;
    float a0 = 0.f, a1 = 0.f, a2 = 0.f, a3 = 0.f;
    for (int k = 0; k < CC; k++) {
        float v = V1[k * CG + j];
        a0 += W2[(i0 + 0) * CC + k] * v;
        a1 += W2[(i0 + 1) * CC + k] * v;
        a2 += W2[(i0 + 2) * CC + k] * v;
        a3 += W2[(i0 + 3) * CC + k] * v;
    }
    g_M[(i0 + 0) * CG + j] = a0; g_M[(i0 + 1) * CG + j] = a1;
    g_M[(i0 + 2) * CG + j] = a2; g_M[(i0 + 3) * CG + j] = a3;
}

// ============ sim + masked top-4 -> ranks 2,3 ==================================
__global__ void k_simtop(const int* __restrict__ labels) {
    int b = blockIdx.x;
    __shared__ float clsb[CC];
    __shared__ float simv[BB];
    __shared__ float rv[256];
    __shared__ int   ri[256];
    int tid = threadIdx.x;
    for (int c = tid; c < CC; c += 256) clsb[c] = g_clsn[b * CC + c];
    __syncthreads();
    int lane = tid & 31, w = tid >> 5;
    int lb = labels[b];
    for (int r = w; r < BB; r += 8) {
        float s = 0.f;
        const float* y = &g_clsn[(size_t)r * CC];
        for (int k = lane; k < CC; k += 32) s += clsb[k] * y[k];
        #pragma unroll
        for (int o = 16; o; o >>= 1) s += __shfl_down_sync(0xffffffffu, s, o);
        if (lane == 0) simv[r] = (labels[r] == lb) ? -FLT_MAX : s;
    }
    __syncthreads();
    for (int it = 0; it < 4; it++) {
        rv[tid] = simv[tid]; ri[tid] = tid; __syncthreads();
        for (int st = 128; st; st >>= 1) {
            if (tid < st) {
                float ov = rv[tid + st]; int oi = ri[tid + st];
                if (ov > rv[tid] || (ov == rv[tid] && oi < ri[tid])) { rv[tid] = ov; ri[tid] = oi; }
            }
            __syncthreads();
        }
        if (tid == 0) {
            if (it >= 2) g_swapidx[b * 2 + (it - 2)] = ri[0];
            simv[ri[0]] = -FLT_MAX;
        }
        __syncthreads();
    }
}

// ============ GEMM1 (mma.sync bf16 x6): H = relu(X@W1+b1) -> split store =======
// CTA tile 128x96, BK=16, 48 k-iters. warps 4m x 2n, warp tile 32x48.
#define G1_LDA 48                          // padded row stride (bytes) for 16 bf16
#define G1_ASZ (128*G1_LDA)                // 6144
#define G1_BSZ (96*G1_LDA)                 // 4608

__global__ __launch_bounds__(256) void k_gemm1(const float* __restrict__ X,
                                               const float* __restrict__ b1) {
    __shared__ __align__(16) char sA[3][G1_ASZ];
    __shared__ __align__(16) char sB[3][G1_BSZ];
    __shared__ float sbias[96];

    int tid = threadIdx.x;
    int wid = tid >> 5, lane = tid & 31;
    int warpm = wid >> 1, warpn = wid & 1;
    int row0 = blockIdx.x * 128;
    int n0 = blockIdx.y * 96;

    if (tid < 96) sbias[tid] = b1[n0 + tid];

    uint32_t sbA = smem_u32(&sA[0][0]);
    uint32_t sbB = smem_u32(&sB[0][0]);

    float acc[2][6][4];
    #pragma unroll
    for (int mt = 0; mt < 2; mt++)
        #pragma unroll
        for (int nt = 0; nt < 6; nt++)
            #pragma unroll
            for (int q = 0; q < 4; q++) acc[mt][nt][q] = 0.f;

    // A prefetch mapping: idx = tid + j*256, row = idx>>2, q = idx&3
    // B prefetch mapping: idx = tid + j*256 (<576), lvl=idx/192, row=(idx%192)>>1, half=idx&1
    float4 pa[2];
    uint4  pb[3];
    bool   pbv[3];
    int    pbl[3], pbr[3], pbh[3];

    auto fetch = [&](int kc) {
        #pragma unroll
        for (int j = 0; j < 2; j++) {
            int idx = tid + j * 256;
            int r = idx >> 2, q = idx & 3;
            pa[j] = *(const float4*)&X[(size_t)(row0 + r) * CC + kc * 16 + q * 4];
        }
        #pragma unroll
        for (int j = 0; j < 3; j++) {
            int idx = tid + j * 256;
            pbv[j] = idx < 576;
            if (pbv[j]) {
                int lvl = idx / 192, rem = idx - lvl * 192;
                int r = rem >> 1, h = rem & 1;
                pbl[j] = lvl; pbr[j] = r; pbh[j] = h;
                pb[j] = *(const uint4*)&g_W1s[lvl][(size_t)(n0 + r) * CC + kc * 16 + h * 8];
            }
        }
    };
    auto stage = [&]() {
        #pragma unroll
        for (int j = 0; j < 2; j++) {
            int idx = tid + j * 256;
            int r = idx >> 2, q = idx & 3;
            float f[4] = {pa[j].x, pa[j].y, pa[j].z, pa[j].w};
            uint32_t ph[2], pm[2], pl[2];
            #pragma unroll
            for (int u = 0; u < 2; u++) {
                __nv_bfloat16 h0, m0, l0, h1, m1, l1;
                split3(f[2*u], h0, m0, l0); split3(f[2*u+1], h1, m1, l1);
                ph[u] = packbf(h0, h1); pm[u] = packbf(m0, m1); pl[u] = packbf(l0, l1);
            }
            int off = r * G1_LDA + q * 8;
            *(uint2*)&sA[0][off] = make_uint2(ph[0], ph[1]);
            *(uint2*)&sA[1][off] = make_uint2(pm[0], pm[1]);
            *(uint2*)&sA[2][off] = make_uint2(pl[0], pl[1]);
        }
        #pragma unroll
        for (int j = 0; j < 3; j++) {
            if (pbv[j])
                *(uint4*)&sB[pbl[j]][pbr[j] * G1_LDA + pbh[j] * 16] = pb[j];
        }
    };

    fetch(0);
    for (int kc = 0; kc < 48; kc++) {
        stage();
        __syncthreads();
        if (kc + 1 < 48) fetch(kc + 1);

        uint32_t af[3][2][4];
        #pragma unroll
        for (int L = 0; L < 3; L++)
            #pragma unroll
            for (int mt = 0; mt < 2; mt++)
                ldsm4(af[L][mt], sbA + L * G1_ASZ +
                      (warpm * 32 + mt * 16 + (lane & 15)) * G1_LDA + (lane >> 4) * 16);
        #pragma unroll
        for (int bL = 0; bL < 3; bL++) {
            uint32_t bf[6][2];
            #pragma unroll
            for (int nt = 0; nt < 6; nt++)
                ldsm2(bf[nt], sbB + bL * G1_BSZ +
                      (warpn * 48 + nt * 8 + (lane & 7)) * G1_LDA + ((lane >> 3) & 1) * 16);
            int nA = 3 - bL;
            #pragma unroll
            for (int aL = 0; aL < 3; aL++) {
                if (aL < nA) {
                    #pragma unroll
                    for (int nt = 0; nt < 6; nt++)
                        #pragma unroll
                        for (int mt = 0; mt < 2; mt++)
                            mma_bf16(acc[mt][nt], af[aL][mt], bf[nt]);
                }
            }
        }
        __syncthreads();
    }

    // epilogue: relu(acc + bias) -> split3 -> g_Hs
    int lr = lane >> 2, lc = (lane & 3) * 2;
    #pragma unroll
    for (int mt = 0; mt < 2; mt++) {
        int r0 = row0 + warpm * 32 + mt * 16 + lr;
        int r1 = r0 + 8;
        #pragma unroll
        for (int nt = 0; nt < 6; nt++) {
            int cl = warpn * 48 + nt * 8 + lc;    // local col in [0,96)
            int col = n0 + cl;                    // global col in [0,192)
            float v00 = fmaxf(acc[mt][nt][0] + sbias[cl], 0.f);
            float v01 = fmaxf(acc[mt][nt][1] + sbias[cl + 1], 0.f);
            float v10 = fmaxf(acc[mt][nt][2] + sbias[cl], 0.f);
            float v11 = fmaxf(acc[mt][nt][3] + sbias[cl + 1], 0.f);
            __nv_bfloat16 h0, m0, l0, h1, m1, l1;
            split3(v00, h0, m0, l0); split3(v01, h1, m1, l1);
            *(uint32_t*)&g_Hs[0][(size_t)r0 * C4 + col] = packbf(h0, h1);
            *(uint32_t*)&g_Hs[1][(size_t)r0 * C4 + col] = packbf(m0, m1);
            *(uint32_t*)&g_Hs[2][(size_t)r0 * C4 + col] = packbf(l0, l1);
            split3(v10, h0, m0, l0); split3(v11, h1, m1, l1);
            *(uint32_t*)&g_Hs[0][(size_t)r1 * C4 + col] = packbf(h0, h1);
            *(uint32_t*)&g_Hs[1][(size_t)r1 * C4 + col] = packbf(m0, m1);
            *(uint32_t*)&g_Hs[2][(size_t)r1 * C4 + col] = packbf(l0, l1);
        }
    }
}

// ============ GEMM2 (mma.sync bf16 x6): partial imp = relu(H@M+d)*V2 ==========
// CTA tile 128x64, BK=16, 12 k-iters. warps 4m x 2n, warp tile 32x32.
#define G2_LDA 48
#define G2_ASZ (128*G2_LDA)                // 6144
#define G2_BSZ (64*G2_LDA)                 // 3072

__global__ __launch_bounds__(256) void k_gemm2(const float* __restrict__ V2) {
    __shared__ __align__(16) char sA[3][G2_ASZ];
    __shared__ __align__(16) char sB[3][G2_BSZ];
    __shared__ float sd[64], sv[64];
    __shared__ float spart[128][2];

    int tid = threadIdx.x;
    int wid = tid >> 5, lane = tid & 31;
    int warpm = wid >> 1, warpn = wid & 1;
    int row0 = blockIdx.x * 128;
    int n0 = blockIdx.y * 64;

    if (tid < 64) { sd[tid] = g_d[n0 + tid]; sv[tid] = V2[n0 + tid]; }

    uint32_t sbA = smem_u32(&sA[0][0]);
    uint32_t sbB = smem_u32(&sB[0][0]);

    float acc[2][4][4];
    #pragma unroll
    for (int mt = 0; mt < 2; mt++)
        #pragma unroll
        for (int nt = 0; nt < 4; nt++)
            #pragma unroll
            for (int q = 0; q < 4; q++) acc[mt][nt][q] = 0.f;

    uint4 pa[3];       // A: lvl = j, row = tid>>1, half = tid&1
    uint4 pb[2];       // B: idx = tid + j*256 (<384), lvl=idx/128, row=(idx%128)>>1, half=idx&1
    bool  pbv[2]; int pbl[2], pbr[2], pbh[2];

    auto fetch = [&](int kc) {
        int r = tid >> 1, h = tid & 1;
        #pragma unroll
        for (int j = 0; j < 3; j++)
            pa[j] = *(const uint4*)&g_Hs[j][(size_t)(row0 + r) * C4 + kc * 16 + h * 8];
        #pragma unroll
        for (int j = 0; j < 2; j++) {
            int idx = tid + j * 256;
            pbv[j] = idx < 384;
            if (pbv[j]) {
                int lvl = idx >> 7, rem = idx & 127;
                int rr = rem >> 1, hh = rem & 1;
                pbl[j] = lvl; pbr[j] = rr; pbh[j] = hh;
                pb[j] = *(const uint4*)&g_M2s[lvl][(size_t)(n0 + rr) * C4 + kc * 16 + hh * 8];
            }
        }
    };
    auto stage = [&]() {
        int r = tid >> 1, h = tid & 1;
        #pragma unroll
        for (int j = 0; j < 3; j++)
            *(uint4*)&sA[j][r * G2_LDA + h * 16] = pa[j];
        #pragma unroll
        for (int j = 0; j < 2; j++)
            if (pbv[j]) *(uint4*)&sB[pbl[j]][pbr[j] * G2_LDA + pbh[j] * 16] = pb[j];
    };

    fetch(0);
    for (int kc = 0; kc < 12; kc++) {
        stage();
        __syncthreads();
        if (kc + 1 < 12) fetch(kc + 1);

        uint32_t af[3][2][4];
        #pragma unroll
        for (int L = 0; L < 3; L++)
            #pragma unroll
            for (int mt = 0; mt < 2; mt++)
                ldsm4(af[L][mt], sbA + L * G2_ASZ +
                      (warpm * 32 + mt * 16 + (lane & 15)) * G2_LDA + (lane >> 4) * 16);
        #pragma unroll
        for (int bL = 0; bL < 3; bL++) {
            uint32_t bf[4][2];
            #pragma unroll
            for (int nt = 0; nt < 4; nt++)
                ldsm2(bf[nt], sbB + bL * G2_BSZ +
                      (warpn * 32 + nt * 8 + (lane & 7)) * G2_LDA + ((lane >> 3) & 1) * 16);
            int nA = 3 - bL;
            #pragma unroll
            for (int aL = 0; aL < 3; aL++) {
                if (aL < nA) {
                    #pragma unroll
                    for (int nt = 0; nt < 4; nt++)
                        #pragma unroll
                        for (int mt = 0; mt < 2; mt++)
                            mma_bf16(acc[mt][nt], af[aL][mt], bf[nt]);
                }
            }
        }
        __syncthreads();
    }

    // epilogue: partial dot with V2 after relu(+d)
    int lr = lane >> 2, lc = (lane & 3) * 2;
    float p[4] = {0.f, 0.f, 0.f, 0.f};
    #pragma unroll
    for (int mt = 0; mt < 2; mt++) {
        #pragma unroll
        for (int nt = 0; nt < 4; nt++) {
            int cl = warpn * 32 + nt * 8 + lc;
            float d0 = sd[cl], d1 = sd[cl + 1], v0 = sv[cl], v1 = sv[cl + 1];
            p[mt * 2 + 0] += fmaxf(acc[mt][nt][0] + d0, 0.f) * v0
                           + fmaxf(acc[mt][nt][1] + d1, 0.f) * v1;
            p[mt * 2 + 1] += fmaxf(acc[mt][nt][2] + d0, 0.f) * v0
                           + fmaxf(acc[mt][nt][3] + d1, 0.f) * v1;
        }
    }
    #pragma unroll
    for (int i = 0; i < 4; i++) {
        p[i] += __shfl_xor_sync(0xffffffffu, p[i], 1);
        p[i] += __shfl_xor_sync(0xffffffffu, p[i], 2);
    }
    if ((lane & 3) == 0) {
        #pragma unroll
        for (int mt = 0; mt < 2; mt++)
            #pragma unroll
            for (int h = 0; h < 2; h++)
                spart[warpm * 32 + mt * 16 + h * 8 + lr][warpn] = p[mt * 2 + h];
    }
    __syncthreads();
    if (tid < 128)
        g_part[(size_t)(row0 + tid) * 4 + blockIdx.y] = spart[tid][0] + spart[tid][1];
}

// ============ reduce partials -> imp ===========================================
__global__ void k_impred(const float* __restrict__ c2) {
    int i = blockIdx.x * 256 + threadIdx.x;
    if (i < TOK)
        g_imp[i] = g_part[(size_t)i * 4] + g_part[(size_t)i * 4 + 1] +
                   g_part[(size_t)i * 4 + 2] + g_part[(size_t)i * 4 + 3] + c2[0];
}

// ============ per-batch top-38 of imp ==========================================
__global__ void k_top38() {
    int b = blockIdx.x;
    __shared__ float v[NN];
    __shared__ float rv[128];
    __shared__ int   ri[128];
    int t = threadIdx.x;
    v[t] = g_imp[b * NN + t];
    if (t == 0) v[128] = g_imp[b * NN + 128];
    __syncthreads();
    for (int it = 0; it < NSW; it++) {
        float bvv = v[t]; int bi = t;
        if (t == 0 && v[128] > bvv) { bvv = v[128]; bi = 128; }
        rv[t] = bvv; ri[t] = bi; __syncthreads();
        for (int st = 64; st; st >>= 1) {
            if (t < st) {
                float ov = rv[t + st]; int oi = ri[t + st];
                if (ov > rv[t] || (ov == rv[t] && oi < ri[t])) { rv[t] = ov; ri[t] = oi; }
            }
            __syncthreads();
        }
        if (t == 0) { g_tp[b * NSW + it] = ri[0]; v[ri[0]] = -FLT_MAX; }
        __syncthreads();
    }
}

// ============ blend swapped rows ===============================================
__global__ void k_blend(const float* __restrict__ feat,
                        const int* __restrict__ swch,
                        float* __restrict__ out) {
    int b = blockIdx.x;
    for (int j = 0; j < NSW; j++) {
        int tp = g_tp[b * NSW + j];
        int patch = tp - 1; if (patch < 0) patch = 0;
        int src = g_swapidx[b * 2 + swch[b * NSW + j]];
        const float* s = &g_clsn[(size_t)src * CC];
        size_t off = ((size_t)b * NN + patch + 1) * CC;
        for (int c = threadIdx.x; c < CC; c += blockDim.x)
            out[off + c] = 0.7f * feat[off + c] + 0.3f * s[c];
    }
}

// ============ launch ===========================================================
extern "C" void kernel_launch(void* const* d_in, const int* in_sizes, int n_in,
                              void* d_out, int out_size) {
    const float* feat   = (const float*)d_in[0];
    const float* W1     = (const float*)d_in[1];
    const float* b1     = (const float*)d_in[2];
    const float* W2     = (const float*)d_in[3];
    const float* b2     = (const float*)d_in[4];
    const float* V1     = (const float*)d_in[5];
    const float* c1     = (const float*)d_in[6];
    const float* V2     = (const float*)d_in[7];
    const float* c2     = (const float*)d_in[8];
    const int*   labels = (const int*)d_in[9];
    const int*   swch   = (const int*)d_in[10];
    float* out = (float*)d_out;

    cudaMemcpyAsync(out, feat, (size_t)TOK * CC * sizeof(float),
                    cudaMemcpyDeviceToDevice);

    k_clsnorm<<<BB, 256>>>(feat);
    k_fold<<<49, 256>>>(W2, V1, b2, c1);
    k_splitW1<<<C4, 256>>>(W1);
    k_splitM<<<CG, 192>>>();
    k_simtop<<<BB, 256>>>(labels);
    k_gemm1<<<dim3(TOK / 128, 2), 256>>>(feat, b1);
    k_gemm2<<<dim3(TOK / 128, 4), 256>>>(V2);
    k_impred<<<(TOK + 255) / 256, 256>>>(c2);
    k_top38<<<BB, 128>>>();
    k_blend<<<BB, 256>>>(feat, swch, out);
}

// round 5
// speedup vs baseline: 1.5841x; 1.5841x over previous
#include <cuda_runtime.h>
#include <cuda_fp16.h>
#include <stdint.h>
#include <float.h>
#include <math.h>

// ---------------- problem constants ----------------
#define BB   256
#define NN   129
#define CC   768
#define C4   192
#define CG   256
#define NSW  38
#define TOK  (BB*NN)   // 33024 = 258 * 128

// Scaling (powers of 2, exact; commute with relu):
//  W1' = 64*W1, b1' = 64*b1     -> H' = 64*H
//  M'  = 256*M                  -> G'' pre-relu = 16384*(H@M), d'' = 16384*d
//  V2' = V2/16384 in epilogue
#define S1 64.0f
#define SM 256.0f
#define SD 16384.0f
#define SVINV (1.0f/16384.0f)

// ---------------- device scratch ----------------
__device__ __align__(16) __half g_W1s[2][C4*CC];          // (64*W1)^T split [192][768]
__device__ __align__(16) __half g_M2s[2][CG*C4];          // (256*W2@V1)^T split [256][192]
__device__ __align__(16) __half g_Hs[2][(size_t)TOK*C4];  // H' = 64*H split
__device__ float g_d[CG];
__device__ float g_clsn[BB*CC];
__device__ float g_part[(size_t)TOK*4];
__device__ float g_imp[TOK];
__device__ int   g_tp[BB*NSW];
__device__ int   g_swapidx[BB*2];

// ---------------- helpers ----------------
__device__ __forceinline__ uint32_t smem_u32(const void* p) {
    uint32_t a;
    asm("{ .reg .u64 t; cvta.to.shared.u64 t, %1; cvt.u32.u64 %0, t; }" : "=r"(a) : "l"(p));
    return a;
}
__device__ __forceinline__ void ldsm4(uint32_t* r, uint32_t addr) {
    asm volatile("ldmatrix.sync.aligned.m8n8.x4.shared.b16 {%0,%1,%2,%3}, [%4];"
                 : "=r"(r[0]), "=r"(r[1]), "=r"(r[2]), "=r"(r[3]) : "r"(addr));
}
__device__ __forceinline__ void ldsm2(uint32_t* r, uint32_t addr) {
    asm volatile("ldmatrix.sync.aligned.m8n8.x2.shared.b16 {%0,%1}, [%2];"
                 : "=r"(r[0]), "=r"(r[1]) : "r"(addr));
}
__device__ __forceinline__ void mma_f16(float* c, const uint32_t* a, const uint32_t* b) {
    asm volatile("mma.sync.aligned.m16n8k16.row.col.f32.f16.f16.f32 "
                 "{%0,%1,%2,%3}, {%4,%5,%6,%7}, {%8,%9}, {%0,%1,%2,%3};"
                 : "+f"(c[0]), "+f"(c[1]), "+f"(c[2]), "+f"(c[3])
                 : "r"(a[0]), "r"(a[1]), "r"(a[2]), "r"(a[3]), "r"(b[0]), "r"(b[1]));
}
__device__ __forceinline__ void split2(float v, __half& h, __half& l) {
    h = __float2half_rn(v);
    l = __float2half_rn(v - __half2float(h));
}
__device__ __forceinline__ uint32_t packh(__half a, __half b) {
    return (uint32_t)__half_as_ushort(a) | ((uint32_t)__half_as_ushort(b) << 16);
}

// ============ split W1 (transposed, scaled by 64) ==============================
__global__ void k_splitW1(const float* __restrict__ W1) {
    int n = blockIdx.x;  // 0..191
    for (int k = threadIdx.x; k < CC; k += 256) {
        float v = W1[k * C4 + n] * S1;
        __half h, l; split2(v, h, l);
        g_W1s[0][n * CC + k] = h; g_W1s[1][n * CC + k] = l;
    }
}

// ============ cls normalization ================================================
__global__ void k_clsnorm(const float* __restrict__ feat) {
    int b = blockIdx.x;
    const float* x = feat + (size_t)b * NN * CC;
    __shared__ float red[256];
    float s = 0.f;
    for (int c = threadIdx.x; c < CC; c += 256) { float v = x[c]; s += v * v; }
    red[threadIdx.x] = s; __syncthreads();
    for (int st = 128; st > 0; st >>= 1) {
        if (threadIdx.x < st) red[threadIdx.x] += red[threadIdx.x + st];
        __syncthreads();
    }
    float inv = 1.0f / fmaxf(sqrtf(red[0]), 1e-12f);
    for (int c = threadIdx.x; c < CC; c += 256) g_clsn[b * CC + c] = x[c] * inv;
}

// ============ fold M = W2@V1 (write split, scaled), d = b2@V1 + c1 =============
__global__ void k_fold(const float* __restrict__ W2, const float* __restrict__ V1,
                       const float* __restrict__ b2, const float* __restrict__ c1) {
    int j = threadIdx.x;  // 0..255 (col of M / row of M^T)
    if (blockIdx.x == 48) {
        float acc = c1[j];
        for (int k = 0; k < CC; k++) acc += b2[k] * V1[k * CG + j];
        g_d[j] = acc;
        return;
    }
    int i0 = blockIdx.x * 4;
    float a[4] = {0.f, 0.f, 0.f, 0.f};
    for (int k = 0; k < CC; k++) {
        float v = V1[k * CG + j];
        a[0] += W2[(i0 + 0) * CC + k] * v;
        a[1] += W2[(i0 + 1) * CC + k] * v;
        a[2] += W2[(i0 + 2) * CC + k] * v;
        a[3] += W2[(i0 + 3) * CC + k] * v;
    }
    #pragma unroll
    for (int r = 0; r < 4; r++) {
        __half h, l; split2(a[r] * SM, h, l);
        g_M2s[0][j * C4 + i0 + r] = h;
        g_M2s[1][j * C4 + i0 + r] = l;
    }
}

// ============ sim + rank-based selection of ranks 2,3 ==========================
__global__ void k_simtop(const int* __restrict__ labels) {
    int b = blockIdx.x;
    __shared__ float clsb[CC];
    __shared__ float simv[BB];
    int tid = threadIdx.x;
    for (int c = tid; c < CC; c += 256) clsb[c] = g_clsn[b * CC + c];
    __syncthreads();
    int lane = tid & 31, w = tid >> 5;
    int lb = labels[b];
    for (int r = w; r < BB; r += 8) {
        float s = 0.f;
        const float* y = &g_clsn[(size_t)r * CC];
        for (int k = lane; k < CC; k += 32) s += clsb[k] * y[k];
        #pragma unroll
        for (int o = 16; o; o >>= 1) s += __shfl_down_sync(0xffffffffu, s, o);
        if (lane == 0) simv[r] = (labels[r] == lb) ? -FLT_MAX : s;
    }
    __syncthreads();
    // rank of my value (descending, ties broken by lower index)
    float mv = simv[tid];
    int rank = 0;
    for (int jj = 0; jj < BB; jj++) {
        float vj = simv[jj];
        rank += (vj > mv) || (vj == mv && jj < tid);
    }
    if (rank == 2) g_swapidx[b * 2 + 0] = tid;
    if (rank == 3) g_swapidx[b * 2 + 1] = tid;
}

// ============ GEMM1: H' = relu(X@W1' + b1') -> fp16 split store ================
// CTA 128x96, BK=32 (24 iters). 8 warps (4m x 2n), warp tile 32x48.
#define G1_LDA 80
#define G1_ASZ (128*G1_LDA)   // 10240
#define G1_BSZ (96*G1_LDA)    // 7680

__global__ __launch_bounds__(256, 2) void k_gemm1(const float* __restrict__ X,
                                                  const float* __restrict__ b1) {
    __shared__ __align__(16) char sA[2][G1_ASZ];
    __shared__ __align__(16) char sB[2][G1_BSZ];
    __shared__ float sbias[96];

    int tid = threadIdx.x;
    int wid = tid >> 5, lane = tid & 31;
    int warpm = wid >> 1, warpn = wid & 1;
    int row0 = blockIdx.x * 128;
    int n0 = blockIdx.y * 96;

    if (tid < 96) sbias[tid] = b1[n0 + tid] * S1;

    uint32_t sbA = smem_u32(&sA[0][0]);
    uint32_t sbB = smem_u32(&sB[0][0]);

    float acc[2][6][4];
    #pragma unroll
    for (int mt = 0; mt < 2; mt++)
        #pragma unroll
        for (int nt = 0; nt < 6; nt++)
            #pragma unroll
            for (int q = 0; q < 4; q++) acc[mt][nt][q] = 0.f;

    float4 pa[4];
    uint4  pb[3];

    auto fetch = [&](int kc) {
        #pragma unroll
        for (int j = 0; j < 4; j++) {
            int idx = tid + j * 256;           // < 1024
            int r = idx >> 3, q = idx & 7;
            pa[j] = *(const float4*)&X[(size_t)(row0 + r) * CC + kc * 32 + q * 4];
        }
        #pragma unroll
        for (int j = 0; j < 3; j++) {
            int idx = tid + j * 256;           // < 768
            int lv = idx / 384, rem = idx - lv * 384;
            int r = rem >> 2, q = rem & 3;
            pb[j] = *(const uint4*)&g_W1s[lv][(size_t)(n0 + r) * CC + kc * 32 + q * 8];
        }
    };
    auto stage = [&]() {
        #pragma unroll
        for (int j = 0; j < 4; j++) {
            int idx = tid + j * 256;
            int r = idx >> 3, q = idx & 7;
            float f[4] = {pa[j].x, pa[j].y, pa[j].z, pa[j].w};
            uint32_t ph[2], pl[2];
            #pragma unroll
            for (int u = 0; u < 2; u++) {
                __half h0, l0, h1, l1;
                split2(f[2*u], h0, l0); split2(f[2*u+1], h1, l1);
                ph[u] = packh(h0, h1); pl[u] = packh(l0, l1);
            }
            int off = r * G1_LDA + q * 8;
            *(uint2*)&sA[0][off] = make_uint2(ph[0], ph[1]);
            *(uint2*)&sA[1][off] = make_uint2(pl[0], pl[1]);
        }
        #pragma unroll
        for (int j = 0; j < 3; j++) {
            int idx = tid + j * 256;
            int lv = idx / 384, rem = idx - lv * 384;
            int r = rem >> 2, q = rem & 3;
            *(uint4*)&sB[lv][r * G1_LDA + q * 16] = pb[j];
        }
    };

    fetch(0);
    for (int kc = 0; kc < 24; kc++) {
        stage();
        __syncthreads();
        if (kc + 1 < 24) fetch(kc + 1);

        #pragma unroll
        for (int s = 0; s < 2; s++) {
            uint32_t af[2][2][4];
            #pragma unroll
            for (int L = 0; L < 2; L++)
                #pragma unroll
                for (int mt = 0; mt < 2; mt++)
                    ldsm4(af[L][mt], sbA + L * G1_ASZ +
                          (warpm * 32 + mt * 16 + (lane & 15)) * G1_LDA +
                          s * 32 + (lane >> 4) * 16);
            #pragma unroll
            for (int bL = 0; bL < 2; bL++) {
                uint32_t bf[6][2];
                #pragma unroll
                for (int nt = 0; nt < 6; nt++)
                    ldsm2(bf[nt], sbB + bL * G1_BSZ +
                          (warpn * 48 + nt * 8 + (lane & 7)) * G1_LDA +
                          s * 32 + ((lane >> 3) & 1) * 16);
                // products: (Ah,Bh), (Al,Bh) for bL=0; (Ah,Bl) for bL=1
                int nA = 2 - bL;
                #pragma unroll
                for (int aL = 0; aL < 2; aL++) {
                    if (aL < nA) {
                        #pragma unroll
                        for (int nt = 0; nt < 6; nt++)
                            #pragma unroll
                            for (int mt = 0; mt < 2; mt++)
                                mma_f16(acc[mt][nt], af[aL][mt], bf[nt]);
                    }
                }
            }
        }
        __syncthreads();
    }

    // epilogue: H' = relu(acc + bias'), split2 -> g_Hs
    int lr = lane >> 2, lc = (lane & 3) * 2;
    #pragma unroll
    for (int mt = 0; mt < 2; mt++) {
        int r0 = row0 + warpm * 32 + mt * 16 + lr;
        int r1 = r0 + 8;
        #pragma unroll
        for (int nt = 0; nt < 6; nt++) {
            int cl = warpn * 48 + nt * 8 + lc;
            int col = n0 + cl;
            float v00 = fmaxf(acc[mt][nt][0] + sbias[cl], 0.f);
            float v01 = fmaxf(acc[mt][nt][1] + sbias[cl + 1], 0.f);
            float v10 = fmaxf(acc[mt][nt][2] + sbias[cl], 0.f);
            float v11 = fmaxf(acc[mt][nt][3] + sbias[cl + 1], 0.f);
            __half h0, l0, h1, l1;
            split2(v00, h0, l0); split2(v01, h1, l1);
            *(uint32_t*)&g_Hs[0][(size_t)r0 * C4 + col] = packh(h0, h1);
            *(uint32_t*)&g_Hs[1][(size_t)r0 * C4 + col] = packh(l0, l1);
            split2(v10, h0, l0); split2(v11, h1, l1);
            *(uint32_t*)&g_Hs[0][(size_t)r1 * C4 + col] = packh(h0, h1);
            *(uint32_t*)&g_Hs[1][(size_t)r1 * C4 + col] = packh(l0, l1);
        }
    }
}

// ============ GEMM2: partial imp = relu(H'@M' + d'') . V2' =====================
// CTA 128x64, BK=32 (6 iters). 8 warps (4m x 2n), warp tile 32x32.
#define G2_LDA 80
#define G2_ASZ (128*G2_LDA)   // 10240
#define G2_BSZ (64*G2_LDA)    // 5120

__global__ __launch_bounds__(256, 2) void k_gemm2(const float* __restrict__ V2) {
    __shared__ __align__(16) char sA[2][G2_ASZ];
    __shared__ __align__(16) char sB[2][G2_BSZ];
    __shared__ float sd[64], sv[64];
    __shared__ float spart[128][2];

    int tid = threadIdx.x;
    int wid = tid >> 5, lane = tid & 31;
    int warpm = wid >> 1, warpn = wid & 1;
    int row0 = blockIdx.x * 128;
    int n0 = blockIdx.y * 64;

    if (tid < 64) { sd[tid] = g_d[n0 + tid] * SD; sv[tid] = V2[n0 + tid] * SVINV; }

    uint32_t sbA = smem_u32(&sA[0][0]);
    uint32_t sbB = smem_u32(&sB[0][0]);

    float acc[2][4][4];
    #pragma unroll
    for (int mt = 0; mt < 2; mt++)
        #pragma unroll
        for (int nt = 0; nt < 4; nt++)
            #pragma unroll
            for (int q = 0; q < 4; q++) acc[mt][nt][q] = 0.f;

    uint4 pa[4], pb[2];

    auto fetch = [&](int kc) {
        #pragma unroll
        for (int j = 0; j < 4; j++) {
            int idx = tid + j * 256;           // < 1024
            int lv = idx >> 9, rem = idx & 511;
            int r = rem >> 2, q = rem & 3;
            pa[j] = *(const uint4*)&g_Hs[lv][(size_t)(row0 + r) * C4 + kc * 32 + q * 8];
        }
        #pragma unroll
        for (int j = 0; j < 2; j++) {
            int idx = tid + j * 256;           // < 512
            int lv = idx >> 8, rem = idx & 255;
            int r = rem >> 2, q = rem & 3;
            pb[j] = *(const uint4*)&g_M2s[lv][(size_t)(n0 + r) * C4 + kc * 32 + q * 8];
        }
    };
    auto stage = [&]() {
        #pragma unroll
        for (int j = 0; j < 4; j++) {
            int idx = tid + j * 256;
            int lv = idx >> 9, rem = idx & 511;
            int r = rem >> 2, q = rem & 3;
            *(uint4*)&sA[lv][r * G2_LDA + q * 16] = pa[j];
        }
        #pragma unroll
        for (int j = 0; j < 2; j++) {
            int idx = tid + j * 256;
            int lv = idx >> 8, rem = idx & 255;
            int r = rem >> 2, q = rem & 3;
            *(uint4*)&sB[lv][r * G2_LDA + q * 16] = pb[j];
        }
    };

    fetch(0);
    for (int kc = 0; kc < 6; kc++) {
        stage();
        __syncthreads();
        if (kc + 1 < 6) fetch(kc + 1);

        #pragma unroll
        for (int s = 0; s < 2; s++) {
            uint32_t af[2][2][4];
            #pragma unroll
            for (int L = 0; L < 2; L++)
                #pragma unroll
                for (int mt = 0; mt < 2; mt++)
                    ldsm4(af[L][mt], sbA + L * G2_ASZ +
                          (warpm * 32 + mt * 16 + (lane & 15)) * G2_LDA +
                          s * 32 + (lane >> 4) * 16);
            #pragma unroll
            for (int bL = 0; bL < 2; bL++) {
                uint32_t bf[4][2];
                #pragma unroll
                for (int nt = 0; nt < 4; nt++)
                    ldsm2(bf[nt], sbB + bL * G2_BSZ +
                          (warpn * 32 + nt * 8 + (lane & 7)) * G2_LDA +
                          s * 32 + ((lane >> 3) & 1) * 16);
                int nA = 2 - bL;
                #pragma unroll
                for (int aL = 0; aL < 2; aL++) {
                    if (aL < nA) {
                        #pragma unroll
                        for (int nt = 0; nt < 4; nt++)
                            #pragma unroll
                            for (int mt = 0; mt < 2; mt++)
                                mma_f16(acc[mt][nt], af[aL][mt], bf[nt]);
                    }
                }
            }
        }
        __syncthreads();
    }

    // epilogue: partial dot with V2' after relu(+d'')
    int lr = lane >> 2, lc = (lane & 3) * 2;
    float p[4] = {0.f, 0.f, 0.f, 0.f};
    #pragma unroll
    for (int mt = 0; mt < 2; mt++) {
        #pragma unroll
        for (int nt = 0; nt < 4; nt++) {
            int cl = warpn * 32 + nt * 8 + lc;
            float d0 = sd[cl], d1 = sd[cl + 1], v0 = sv[cl], v1 = sv[cl + 1];
            p[mt * 2 + 0] += fmaxf(acc[mt][nt][0] + d0, 0.f) * v0
                           + fmaxf(acc[mt][nt][1] + d1, 0.f) * v1;
            p[mt * 2 + 1] += fmaxf(acc[mt][nt][2] + d0, 0.f) * v0
                           + fmaxf(acc[mt][nt][3] + d1, 0.f) * v1;
        }
    }
    #pragma unroll
    for (int i = 0; i < 4; i++) {
        p[i] += __shfl_xor_sync(0xffffffffu, p[i], 1);
        p[i] += __shfl_xor_sync(0xffffffffu, p[i], 2);
    }
    if ((lane & 3) == 0) {
        #pragma unroll
        for (int mt = 0; mt < 2; mt++)
            #pragma unroll
            for (int h = 0; h < 2; h++)
                spart[warpm * 32 + mt * 16 + h * 8 + lr][warpn] = p[mt * 2 + h];
    }
    __syncthreads();
    if (tid < 128)
        g_part[(size_t)(row0 + tid) * 4 + blockIdx.y] = spart[tid][0] + spart[tid][1];
}

// ============ reduce partials -> imp ===========================================
__global__ void k_impred(const float* __restrict__ c2) {
    int i = blockIdx.x * 256 + threadIdx.x;
    if (i < TOK)
        g_imp[i] = g_part[(size_t)i * 4] + g_part[(size_t)i * 4 + 1] +
                   g_part[(size_t)i * 4 + 2] + g_part[(size_t)i * 4 + 3] + c2[0];
}

// ============ rank-based top-38 (softmax monotonic -> skipped) =================
__global__ void k_top38() {
    int b = blockIdx.x;
    __shared__ float v[NN];
    int t = threadIdx.x;  // 192 threads
    if (t < NN) v[t] = g_imp[b * NN + t];
    __syncthreads();
    if (t < NN) {
        float mv = v[t];
        int rank = 0;
        for (int jj = 0; jj < NN; jj++) {
            float vj = v[jj];
            rank += (vj > mv) || (vj == mv && jj < t);
        }
        if (rank < NSW) g_tp[b * NSW + rank] = t;
    }
}

// ============ blend swapped rows (parallel over j, collision-guarded) ==========
__global__ void k_blend(const float* __restrict__ feat,
                        const int* __restrict__ swch,
                        float* __restrict__ out) {
    int b = blockIdx.x, j = blockIdx.y;
    int tp = g_tp[b * NSW + j];
    if (tp <= 1) {
        // adj collision possible only between tp==0 and tp==1 (both -> row 1);
        // reference scatter: later j wins -> skip if any later j has tp<=1.
        for (int j2 = j + 1; j2 < NSW; j2++)
            if (g_tp[b * NSW + j2] <= 1) return;
    }
    int patch = tp - 1; if (patch < 0) patch = 0;
    int src = g_swapidx[b * 2 + swch[b * NSW + j]];
    const float4* s = (const float4*)&g_clsn[(size_t)src * CC];
    size_t off = ((size_t)b * NN + patch + 1) * CC;
    const float4* f = (const float4*)(feat + off);
    float4* o = (float4*)(out + off);
    int t = threadIdx.x;  // 192 threads, one float4 each
    float4 fv = f[t], sv = s[t];
    o[t] = make_float4(0.7f * fv.x + 0.3f * sv.x, 0.7f * fv.y + 0.3f * sv.y,
                       0.7f * fv.z + 0.3f * sv.z, 0.7f * fv.w + 0.3f * sv.w);
}

// ============ launch ===========================================================
extern "C" void kernel_launch(void* const* d_in, const int* in_sizes, int n_in,
                              void* d_out, int out_size) {
    const float* feat   = (const float*)d_in[0];
    const float* W1     = (const float*)d_in[1];
    const float* b1     = (const float*)d_in[2];
    const float* W2     = (const float*)d_in[3];
    const float* b2     = (const float*)d_in[4];
    const float* V1     = (const float*)d_in[5];
    const float* c1     = (const float*)d_in[6];
    const float* V2     = (const float*)d_in[7];
    const float* c2     = (const float*)d_in[8];
    const int*   labels = (const int*)d_in[9];
    const int*   swch   = (const int*)d_in[10];
    float* out = (float*)d_out;

    cudaMemcpyAsync(out, feat, (size_t)TOK * CC * sizeof(float),
                    cudaMemcpyDeviceToDevice);

    k_clsnorm<<<BB, 256>>>(feat);
    k_fold<<<49, 256>>>(W2, V1, b2, c1);
    k_splitW1<<<C4, 256>>>(W1);
    k_simtop<<<BB, 256>>>(labels);
    k_gemm1<<<dim3(TOK / 128, 2), 256>>>(feat, b1);
    k_gemm2<<<dim3(TOK / 128, 4), 256>>>(V2);
    k_impred<<<(TOK + 255) / 256, 256>>>(c2);
    k_top38<<<BB, 192>>>();
    k_blend<<<dim3(BB, NSW), 192>>>(feat, swch, out);
}

// round 6
// speedup vs baseline: 1.5888x; 1.0030x over previous
#include <cuda_runtime.h>
#include <cuda_fp16.h>
#include <stdint.h>
#include <float.h>
#include <math.h>

// ---------------- problem constants ----------------
#define BB   256
#define NN   129
#define CC   768
#define C4   192
#define CG   256
#define NSW  38
#define TOK  (BB*NN)   // 33024 = 258 * 128

// Scaling (powers of 2, exact; commute with relu):
//  W1' = 64*W1, b1' = 64*b1 -> H' = 64*H ; M' = 256*M -> d'' = 16384*d ; V2' = V2/16384
#define S1 64.0f
#define SM 256.0f
#define SD 16384.0f
#define SVINV (1.0f/16384.0f)

// ---------------- device scratch ----------------
__device__ __align__(16) __half g_W1s[2][C4*CC];          // (64*W1)^T split [192][768]
__device__ __align__(16) __half g_M2s[2][CG*C4];          // (256*W2@V1)^T split [256][192]
__device__ __align__(16) __half g_Hs[2][(size_t)TOK*C4];  // H' split
__device__ float g_d[CG];
__device__ float g_clsn[BB*CC];
__device__ float g_sim[BB*BB];
__device__ float g_part[(size_t)TOK*4];
__device__ int   g_tp[BB*NSW];
__device__ int   g_swapidx[BB*2];

// ---------------- helpers ----------------
__device__ __forceinline__ uint32_t smem_u32(const void* p) {
    uint32_t a;
    asm("{ .reg .u64 t; cvta.to.shared.u64 t, %1; cvt.u32.u64 %0, t; }" : "=r"(a) : "l"(p));
    return a;
}
__device__ __forceinline__ void ldsm4(uint32_t* r, uint32_t addr) {
    asm volatile("ldmatrix.sync.aligned.m8n8.x4.shared.b16 {%0,%1,%2,%3}, [%4];"
                 : "=r"(r[0]), "=r"(r[1]), "=r"(r[2]), "=r"(r[3]) : "r"(addr));
}
__device__ __forceinline__ void ldsm2(uint32_t* r, uint32_t addr) {
    asm volatile("ldmatrix.sync.aligned.m8n8.x2.shared.b16 {%0,%1}, [%2];"
                 : "=r"(r[0]), "=r"(r[1]) : "r"(addr));
}
__device__ __forceinline__ void mma_f16(float* c, const uint32_t* a, const uint32_t* b) {
    asm volatile("mma.sync.aligned.m16n8k16.row.col.f32.f16.f16.f32 "
                 "{%0,%1,%2,%3}, {%4,%5,%6,%7}, {%8,%9}, {%0,%1,%2,%3};"
                 : "+f"(c[0]), "+f"(c[1]), "+f"(c[2]), "+f"(c[3])
                 : "r"(a[0]), "r"(a[1]), "r"(a[2]), "r"(a[3]), "r"(b[0]), "r"(b[1]));
}
__device__ __forceinline__ void split2(float v, __half& h, __half& l) {
    h = __float2half_rn(v);
    l = __float2half_rn(v - __half2float(h));
}
__device__ __forceinline__ uint32_t packh(__half a, __half b) {
    return (uint32_t)__half_as_ushort(a) | ((uint32_t)__half_as_ushort(b) << 16);
}

// ============ split W1 (transposed, scaled by 64) ==============================
__global__ void k_splitW1(const float* __restrict__ W1) {
    int n = blockIdx.x;  // 0..191
    for (int k = threadIdx.x; k < CC; k += 256) {
        float v = W1[k * C4 + n] * S1;
        __half h, l; split2(v, h, l);
        g_W1s[0][n * CC + k] = h; g_W1s[1][n * CC + k] = l;
    }
}

// ============ cls normalization ================================================
__global__ void k_clsnorm(const float* __restrict__ feat) {
    int b = blockIdx.x;
    const float* x = feat + (size_t)b * NN * CC;
    __shared__ float red[256];
    float s = 0.f;
    for (int c = threadIdx.x; c < CC; c += 256) { float v = x[c]; s += v * v; }
    red[threadIdx.x] = s; __syncthreads();
    for (int st = 128; st > 0; st >>= 1) {
        if (threadIdx.x < st) red[threadIdx.x] += red[threadIdx.x + st];
        __syncthreads();
    }
    float inv = 1.0f / fmaxf(sqrtf(red[0]), 1e-12f);
    for (int c = threadIdx.x; c < CC; c += 256) g_clsn[b * CC + c] = x[c] * inv;
}

// ============ d = b2@V1 + c1 ===================================================
__global__ void k_d(const float* __restrict__ V1, const float* __restrict__ b2,
                    const float* __restrict__ c1) {
    int j = threadIdx.x;  // 256 threads
    float acc = c1[j];
    #pragma unroll 8
    for (int k = 0; k < CC; k++) acc += b2[k] * V1[k * CG + j];
    g_d[j] = acc;
}

// ============ fold: M2s[j][i] = split((W2@V1)[i][j] * 256), tiled ==============
__global__ void k_fold(const float* __restrict__ W2, const float* __restrict__ V1) {
    __shared__ float sV[64][65];   // [k][j]
    __shared__ float sW[64][65];   // [i][k]
    int tx = threadIdx.x & 15, ty = threadIdx.x >> 4;
    int tid = threadIdx.x;
    int j0 = blockIdx.x * 64, i0 = blockIdx.y * 64;

    float acc[4][4];
    #pragma unroll
    for (int a = 0; a < 4; a++)
        #pragma unroll
        for (int bq = 0; bq < 4; bq++) acc[a][bq] = 0.f;

    for (int k0 = 0; k0 < CC; k0 += 64) {
        #pragma unroll
        for (int q = 0; q < 16; q++) {
            int idx = tid + q * 256;
            int r = idx >> 6, c = idx & 63;
            sV[r][c] = V1[(size_t)(k0 + r) * CG + j0 + c];
            sW[r][c] = W2[(size_t)(i0 + r) * CC + k0 + c];
        }
        __syncthreads();
        #pragma unroll 8
        for (int kk = 0; kk < 64; kk++) {
            float bj[4], ai[4];
            #pragma unroll
            for (int q = 0; q < 4; q++) { bj[q] = sV[kk][tx * 4 + q]; ai[q] = sW[ty * 4 + q][kk]; }
            #pragma unroll
            for (int a = 0; a < 4; a++)
                #pragma unroll
                for (int bq = 0; bq < 4; bq++) acc[a][bq] += ai[a] * bj[bq];
        }
        __syncthreads();
    }
    #pragma unroll
    for (int a = 0; a < 4; a++) {
        int i = i0 + ty * 4 + a;
        #pragma unroll
        for (int bq = 0; bq < 4; bq++) {
            int j = j0 + tx * 4 + bq;
            __half h, l; split2(acc[a][bq] * SM, h, l);
            g_M2s[0][j * C4 + i] = h;
            g_M2s[1][j * C4 + i] = l;
        }
    }
}

// ============ sim = clsn @ clsn^T, tiled =======================================
__global__ void k_sim() {
    __shared__ float sA[64][65];   // [row][k]
    __shared__ float sB[64][65];   // [row][k]
    int tx = threadIdx.x & 15, ty = threadIdx.x >> 4;
    int tid = threadIdx.x;
    int r0 = blockIdx.y * 64, c0 = blockIdx.x * 64;

    float acc[4][4];
    #pragma unroll
    for (int a = 0; a < 4; a++)
        #pragma unroll
        for (int bq = 0; bq < 4; bq++) acc[a][bq] = 0.f;

    for (int k0 = 0; k0 < CC; k0 += 64) {
        #pragma unroll
        for (int q = 0; q < 16; q++) {
            int idx = tid + q * 256;
            int r = idx >> 6, c = idx & 63;
            sA[r][c] = g_clsn[(size_t)(r0 + r) * CC + k0 + c];
            sB[r][c] = g_clsn[(size_t)(c0 + r) * CC + k0 + c];
        }
        __syncthreads();
        #pragma unroll 8
        for (int kk = 0; kk < 64; kk++) {
            float ai[4], bj[4];
            #pragma unroll
            for (int q = 0; q < 4; q++) { ai[q] = sA[ty * 4 + q][kk]; bj[q] = sB[tx * 4 + q][kk]; }
            #pragma unroll
            for (int a = 0; a < 4; a++)
                #pragma unroll
                for (int bq = 0; bq < 4; bq++) acc[a][bq] += ai[a] * bj[bq];
        }
        __syncthreads();
    }
    #pragma unroll
    for (int a = 0; a < 4; a++)
        #pragma unroll
        for (int bq = 0; bq < 4; bq++)
            g_sim[(size_t)(r0 + ty * 4 + a) * BB + c0 + tx * 4 + bq] = acc[a][bq];
}

// ============ rank 2,3 of masked sim row =======================================
__global__ void k_rank23(const int* __restrict__ labels) {
    int b = blockIdx.x, t = threadIdx.x;
    __shared__ float v[BB];
    int lb = labels[b];
    float s = g_sim[(size_t)b * BB + t];
    v[t] = (labels[t] == lb) ? -FLT_MAX : s;
    __syncthreads();
    float mv = v[t];
    int rank = 0;
    for (int j = 0; j < BB; j++) {
        float vj = v[j];
        rank += (vj > mv) || (vj == mv && j < t);
    }
    if (rank == 2) g_swapidx[b * 2 + 0] = t;
    if (rank == 3) g_swapidx[b * 2 + 1] = t;
}

// ============ GEMM1: H' = relu(X@W1' + b1'), fused out-copy, double-buffered ===
// CTA 128x96, BK=32 (24 iters). 8 warps (4m x 2n), warp tile 32x48.
#define G1_LDA 80
#define G1_AL  (128*G1_LDA)        // 10240 per level
#define G1_AST (2*G1_AL)           // 20480 per stage
#define G1_BL  (96*G1_LDA)         // 7680
#define G1_BST (2*G1_BL)           // 15360
#define G1_SMEM (2*G1_AST + 2*G1_BST + 512)   // 72704

__global__ __launch_bounds__(256, 2) void k_gemm1(const float* __restrict__ X,
                                                  const float* __restrict__ b1,
                                                  float* __restrict__ out) {
    extern __shared__ __align__(16) char smem[];
    char* sA = smem;
    char* sB = smem + 2 * G1_AST;
    float* sbias = (float*)(smem + 2 * G1_AST + 2 * G1_BST);

    int tid = threadIdx.x;
    int wid = tid >> 5, lane = tid & 31;
    int warpm = wid >> 1, warpn = wid & 1;
    int row0 = blockIdx.x * 128;
    int n0 = blockIdx.y * 96;
    bool wout = (blockIdx.y == 0);

    if (tid < 96) sbias[tid] = b1[n0 + tid] * S1;

    uint32_t sbA = smem_u32(sA);
    uint32_t sbB = smem_u32(sB);

    float acc[2][6][4];
    #pragma unroll
    for (int mt = 0; mt < 2; mt++)
        #pragma unroll
        for (int nt = 0; nt < 6; nt++)
            #pragma unroll
            for (int q = 0; q < 4; q++) acc[mt][nt][q] = 0.f;

    float4 pa[4];
    uint4  pb[3];

    auto fetch = [&](int kc) {
        #pragma unroll
        for (int j = 0; j < 4; j++) {
            int idx = tid + j * 256;
            int r = idx >> 3, q = idx & 7;
            pa[j] = *(const float4*)&X[(size_t)(row0 + r) * CC + kc * 32 + q * 4];
        }
        #pragma unroll
        for (int j = 0; j < 3; j++) {
            int idx = tid + j * 256;
            int lv = idx / 384, rem = idx - lv * 384;
            int r = rem >> 2, q = rem & 3;
            pb[j] = *(const uint4*)&g_W1s[lv][(size_t)(n0 + r) * CC + kc * 32 + q * 8];
        }
    };
    auto stage = [&](int kc, int st) {
        #pragma unroll
        for (int j = 0; j < 4; j++) {
            int idx = tid + j * 256;
            int r = idx >> 3, q = idx & 7;
            if (wout)
                *(float4*)&out[(size_t)(row0 + r) * CC + kc * 32 + q * 4] = pa[j];
            float f[4] = {pa[j].x, pa[j].y, pa[j].z, pa[j].w};
            uint32_t ph[2], pl[2];
            #pragma unroll
            for (int u = 0; u < 2; u++) {
                __half h0, l0, h1, l1;
                split2(f[2*u], h0, l0); split2(f[2*u+1], h1, l1);
                ph[u] = packh(h0, h1); pl[u] = packh(l0, l1);
            }
            int off = st * G1_AST + r * G1_LDA + q * 8;
            *(uint2*)&sA[off] = make_uint2(ph[0], ph[1]);
            *(uint2*)&sA[off + G1_AL] = make_uint2(pl[0], pl[1]);
        }
        #pragma unroll
        for (int j = 0; j < 3; j++) {
            int idx = tid + j * 256;
            int lv = idx / 384, rem = idx - lv * 384;
            int r = rem >> 2, q = rem & 3;
            *(uint4*)&sB[st * G1_BST + lv * G1_BL + r * G1_LDA + q * 16] = pb[j];
        }
    };

    fetch(0);
    stage(0, 0);
    __syncthreads();

    for (int kc = 0; kc < 24; kc++) {
        int st = kc & 1;
        if (kc + 1 < 24) fetch(kc + 1);

        #pragma unroll
        for (int s = 0; s < 2; s++) {
            uint32_t af[2][2][4];
            #pragma unroll
            for (int L = 0; L < 2; L++)
                #pragma unroll
                for (int mt = 0; mt < 2; mt++)
                    ldsm4(af[L][mt], sbA + st * G1_AST + L * G1_AL +
                          (warpm * 32 + mt * 16 + (lane & 15)) * G1_LDA +
                          s * 32 + (lane >> 4) * 16);
            #pragma unroll
            for (int bL = 0; bL < 2; bL++) {
                uint32_t bf[6][2];
                #pragma unroll
                for (int nt = 0; nt < 6; nt++)
                    ldsm2(bf[nt], sbB + st * G1_BST + bL * G1_BL +
                          (warpn * 48 + nt * 8 + (lane & 7)) * G1_LDA +
                          s * 32 + ((lane >> 3) & 1) * 16);
                int nA = 2 - bL;
                #pragma unroll
                for (int aL = 0; aL < 2; aL++) {
                    if (aL < nA) {
                        #pragma unroll
                        for (int nt = 0; nt < 6; nt++)
                            #pragma unroll
                            for (int mt = 0; mt < 2; mt++)
                                mma_f16(acc[mt][nt], af[aL][mt], bf[nt]);
                    }
                }
            }
        }
        if (kc + 1 < 24) stage(kc + 1, (kc + 1) & 1);
        __syncthreads();
    }

    // epilogue: H' = relu(acc + bias'), split2 -> g_Hs
    int lr = lane >> 2, lc = (lane & 3) * 2;
    #pragma unroll
    for (int mt = 0; mt < 2; mt++) {
        int r0 = row0 + warpm * 32 + mt * 16 + lr;
        int r1 = r0 + 8;
        #pragma unroll
        for (int nt = 0; nt < 6; nt++) {
            int cl = warpn * 48 + nt * 8 + lc;
            int col = n0 + cl;
            float v00 = fmaxf(acc[mt][nt][0] + sbias[cl], 0.f);
            float v01 = fmaxf(acc[mt][nt][1] + sbias[cl + 1], 0.f);
            float v10 = fmaxf(acc[mt][nt][2] + sbias[cl], 0.f);
            float v11 = fmaxf(acc[mt][nt][3] + sbias[cl + 1], 0.f);
            __half h0, l0, h1, l1;
            split2(v00, h0, l0); split2(v01, h1, l1);
            *(uint32_t*)&g_Hs[0][(size_t)r0 * C4 + col] = packh(h0, h1);
            *(uint32_t*)&g_Hs[1][(size_t)r0 * C4 + col] = packh(l0, l1);
            split2(v10, h0, l0); split2(v11, h1, l1);
            *(uint32_t*)&g_Hs[0][(size_t)r1 * C4 + col] = packh(h0, h1);
            *(uint32_t*)&g_Hs[1][(size_t)r1 * C4 + col] = packh(l0, l1);
        }
    }
}

// ============ GEMM2: partial imp = relu(H'@M' + d'') . V2' =====================
// CTA 128x64, BK=32 (6 iters). B preloaded (k-invariant), A double-buffered.
#define G2_LDA 80
#define G2_AL  (128*G2_LDA)        // 10240
#define G2_AST (2*G2_AL)           // 20480
#define G2_LDB 400                 // 192 halfs + pad
#define G2_BL  (64*G2_LDB)         // 25600
#define G2_SMEM (2*G2_AST + 2*G2_BL + 2048)   // 40960+51200+2048 = 94208

__global__ __launch_bounds__(256, 2) void k_gemm2(const float* __restrict__ V2) {
    extern __shared__ __align__(16) char smem[];
    char* sA = smem;
    char* sB = smem + 2 * G2_AST;
    float* sd = (float*)(smem + 2 * G2_AST + 2 * G2_BL);
    float* sv = sd + 64;
    float* spart = sv + 64;        // 128*2 floats

    int tid = threadIdx.x;
    int wid = tid >> 5, lane = tid & 31;
    int warpm = wid >> 1, warpn = wid & 1;
    int row0 = blockIdx.x * 128;
    int n0 = blockIdx.y * 64;

    if (tid < 64) { sd[tid] = g_d[n0 + tid] * SD; sv[tid] = V2[n0 + tid] * SVINV; }

    // preload B: 2 levels x 64 rows x 192 halfs
    #pragma unroll
    for (int q = 0; q < 12; q++) {
        int idx = tid + q * 256;           // < 3072
        int lv = idx >= 1536;
        int rem = idx - lv * 1536;
        int r = rem / 24, c = rem - r * 24;
        uint4 v = *(const uint4*)&g_M2s[lv][(size_t)(n0 + r) * C4 + c * 8];
        *(uint4*)&sB[lv * G2_BL + r * G2_LDB + c * 16] = v;
    }

    uint32_t sbA = smem_u32(sA);
    uint32_t sbB = smem_u32(sB);

    float acc[2][4][4];
    #pragma unroll
    for (int mt = 0; mt < 2; mt++)
        #pragma unroll
        for (int nt = 0; nt < 4; nt++)
            #pragma unroll
            for (int q = 0; q < 4; q++) acc[mt][nt][q] = 0.f;

    uint4 pa[4];
    auto fetch = [&](int kc) {
        #pragma unroll
        for (int j = 0; j < 4; j++) {
            int idx = tid + j * 256;
            int lv = idx >> 9, rem = idx & 511;
            int r = rem >> 2, q = rem & 3;
            pa[j] = *(const uint4*)&g_Hs[lv][(size_t)(row0 + r) * C4 + kc * 32 + q * 8];
        }
    };
    auto stage = [&](int st) {
        #pragma unroll
        for (int j = 0; j < 4; j++) {
            int idx = tid + j * 256;
            int lv = idx >> 9, rem = idx & 511;
            int r = rem >> 2, q = rem & 3;
            *(uint4*)&sA[st * G2_AST + lv * G2_AL + r * G2_LDA + q * 16] = pa[j];
        }
    };

    fetch(0);
    stage(0);
    __syncthreads();

    for (int kc = 0; kc < 6; kc++) {
        int st = kc & 1;
        if (kc + 1 < 6) fetch(kc + 1);

        #pragma unroll
        for (int s = 0; s < 2; s++) {
            uint32_t af[2][2][4];
            #pragma unroll
            for (int L = 0; L < 2; L++)
                #pragma unroll
                for (int mt = 0; mt < 2; mt++)
                    ldsm4(af[L][mt], sbA + st * G2_AST + L * G2_AL +
                          (warpm * 32 + mt * 16 + (lane & 15)) * G2_LDA +
                          s * 32 + (lane >> 4) * 16);
            #pragma unroll
            for (int bL = 0; bL < 2; bL++) {
                uint32_t bf[4][2];
                #pragma unroll
                for (int nt = 0; nt < 4; nt++)
                    ldsm2(bf[nt], sbB + bL * G2_BL +
                          (warpn * 32 + nt * 8 + (lane & 7)) * G2_LDB +
                          kc * 64 + s * 32 + ((lane >> 3) & 1) * 16);
                int nA = 2 - bL;
                #pragma unroll
                for (int aL = 0; aL < 2; aL++) {
                    if (aL < nA) {
                        #pragma unroll
                        for (int nt = 0; nt < 4; nt++)
                            #pragma unroll
                            for (int mt = 0; mt < 2; mt++)
                                mma_f16(acc[mt][nt], af[aL][mt], bf[nt]);
                    }
                }
            }
        }
        if (kc + 1 < 6) stage((kc + 1) & 1);
        __syncthreads();
    }

    // epilogue: partial dot with V2' after relu(+d'')
    int lr = lane >> 2, lc = (lane & 3) * 2;
    float p[4] = {0.f, 0.f, 0.f, 0.f};
    #pragma unroll
    for (int mt = 0; mt < 2; mt++) {
        #pragma unroll
        for (int nt = 0; nt < 4; nt++) {
            int cl = warpn * 32 + nt * 8 + lc;
            float d0 = sd[cl], d1 = sd[cl + 1], v0 = sv[cl], v1 = sv[cl + 1];
            p[mt * 2 + 0] += fmaxf(acc[mt][nt][0] + d0, 0.f) * v0
                           + fmaxf(acc[mt][nt][1] + d1, 0.f) * v1;
            p[mt * 2 + 1] += fmaxf(acc[mt][nt][2] + d0, 0.f) * v0
                           + fmaxf(acc[mt][nt][3] + d1, 0.f) * v1;
        }
    }
    #pragma unroll
    for (int i = 0; i < 4; i++) {
        p[i] += __shfl_xor_sync(0xffffffffu, p[i], 1);
        p[i] += __shfl_xor_sync(0xffffffffu, p[i], 2);
    }
    if ((lane & 3) == 0) {
        #pragma unroll
        for (int mt = 0; mt < 2; mt++)
            #pragma unroll
            for (int h = 0; h < 2; h++)
                spart[(warpm * 32 + mt * 16 + h * 8 + lr) * 2 + warpn] = p[mt * 2 + h];
    }
    __syncthreads();
    if (tid < 128)
        g_part[(size_t)(row0 + tid) * 4 + blockIdx.y] = spart[tid * 2] + spart[tid * 2 + 1];
}

// ============ rank-based top-38 (softmax + c2 shift both rank-invariant) =======
__global__ void k_top38() {
    int b = blockIdx.x;
    __shared__ float v[NN];
    int t = threadIdx.x;  // 192 threads
    if (t < NN) {
        size_t r = (size_t)(b * NN + t) * 4;
        v[t] = g_part[r] + g_part[r + 1] + g_part[r + 2] + g_part[r + 3];
    }
    __syncthreads();
    if (t < NN) {
        float mv = v[t];
        int rank = 0;
        for (int jj = 0; jj < NN; jj++) {
            float vj = v[jj];
            rank += (vj > mv) || (vj == mv && jj < t);
        }
        if (rank < NSW) g_tp[b * NSW + rank] = t;
    }
}

// ============ blend swapped rows (parallel over j, collision-guarded) ==========
__global__ void k_blend(const float* __restrict__ feat,
                        const int* __restrict__ swch,
                        float* __restrict__ out) {
    int b = blockIdx.x, j = blockIdx.y;
    int tp = g_tp[b * NSW + j];
    if (tp <= 1) {
        for (int j2 = j + 1; j2 < NSW; j2++)
            if (g_tp[b * NSW + j2] <= 1) return;   // later j wins the adj==0 slot
    }
    int patch = tp - 1; if (patch < 0) patch = 0;
    int src = g_swapidx[b * 2 + swch[b * NSW + j]];
    const float4* s = (const float4*)&g_clsn[(size_t)src * CC];
    size_t off = ((size_t)b * NN + patch + 1) * CC;
    const float4* f = (const float4*)(feat + off);
    float4* o = (float4*)(out + off);
    int t = threadIdx.x;  // 192 threads
    float4 fv = f[t], sv = s[t];
    o[t] = make_float4(0.7f * fv.x + 0.3f * sv.x, 0.7f * fv.y + 0.3f * sv.y,
                       0.7f * fv.z + 0.3f * sv.z, 0.7f * fv.w + 0.3f * sv.w);
}

// ============ launch ===========================================================
extern "C" void kernel_launch(void* const* d_in, const int* in_sizes, int n_in,
                              void* d_out, int out_size) {
    const float* feat   = (const float*)d_in[0];
    const float* W1     = (const float*)d_in[1];
    const float* b1     = (const float*)d_in[2];
    const float* W2     = (const float*)d_in[3];
    const float* b2     = (const float*)d_in[4];
    const float* V1     = (const float*)d_in[5];
    const float* c1     = (const float*)d_in[6];
    const float* V2     = (const float*)d_in[7];
    const int*   labels = (const int*)d_in[9];
    const int*   swch   = (const int*)d_in[10];
    float* out = (float*)d_out;

    cudaFuncSetAttribute(k_gemm1, cudaFuncAttributeMaxDynamicSharedMemorySize, G1_SMEM);
    cudaFuncSetAttribute(k_gemm2, cudaFuncAttributeMaxDynamicSharedMemorySize, G2_SMEM);

    k_clsnorm<<<BB, 256>>>(feat);                       // 1
    k_fold<<<dim3(4, 3), 256>>>(W2, V1);                // 2
    k_d<<<1, 256>>>(V1, b2, c1);                        // 3
    k_splitW1<<<C4, 256>>>(W1);                         // 4
    k_gemm1<<<dim3(TOK / 128, 2), 256, G1_SMEM>>>(feat, b1, out);   // 5 (ncu capture)
    k_sim<<<dim3(4, 4), 256>>>();                       // 6
    k_rank23<<<BB, 256>>>(labels);                      // 7
    k_gemm2<<<dim3(TOK / 128, 4), 256, G2_SMEM>>>(V2);  // 8
    k_top38<<<BB, 192>>>();                             // 9
    k_blend<<<dim3(BB, NSW), 192>>>(feat, swch, out);   // 10
}